// round 16
// baseline (speedup 1.0000x reference)
#include <cuda_runtime.h>
#include <math.h>

#define BB 16
#define NN 2048   // samp points (rows)
#define MM 8192   // ref points (cols)

// Scratch: partial minima (written, never read-modify — no init needed)
// Values UNCLAMPED (can be tiny-negative); final1 clamps.
__device__ float g_row[4][BB][NN];       // per m-quarter: min d2 for each samp point
__device__ float g_col[10][BB][MM];      // per in-group slot j: min d2 for each ref point
__device__ float g_part[BB][36][2];      // stage-1 partial sums

typedef unsigned long long ull;

__device__ __forceinline__ ull pack2(float v) {
    ull r;
    asm("mov.b64 %0, {%1, %1};" : "=l"(r) : "f"(v));
    return r;
}
__device__ __forceinline__ ull pack_ab(float a, float b) {
    ull r;
    asm("mov.b64 %0, {%1, %2};" : "=l"(r) : "f"(a), "f"(b));
    return r;
}
__device__ __forceinline__ ull ffma2(ull a, ull b, ull c) {
    ull d;
    asm("fma.rn.f32x2 %0, %1, %2, %3;" : "=l"(d) : "l"(a), "l"(b), "l"(c));
    return d;
}
__device__ __forceinline__ ull add2(ull a, ull b) {
    ull d;
    asm("add.rn.f32x2 %0, %1, %2;" : "=l"(d) : "l"(a), "l"(b));
    return d;
}
__device__ __forceinline__ float2 unpack2(ull v) {
    float2 f;
    asm("mov.b64 {%0, %1}, %2;" : "=f"(f.x), "=f"(f.y) : "l"(v));
    return f;
}

#define MAXROWS 228   // max rows per block (2048/9 rounded up)

// Single-wave kernel: EXACTLY 592 blocks = 148 SMs x 4 resident.
// 64 groups g=(b,mq) of 2048 rows x 2048 cols; batches 0-3: 10 blocks/group,
// batches 4-15: 9 blocks/group. Block j covers rows [j*2048/nb,(j+1)*2048/nb).
// Lane owns 8 cols as 4 f32x2 pairs. SOFTWARE-PIPELINED mainloop: iteration r
// issues row r's packed FMA chains (fma pipe) interleaved with row r-1's
// min/REDUX work (alu pipe) — the groups are independent, so the two pipes
// can dual-issue instead of running as phase-locked single-pipe clumps.
__global__ void __launch_bounds__(256, 4) chamfer_fused(const float* __restrict__ samp,
                                                        const float* __restrict__ ref) {
    __shared__ float4 stage[512];            // ref staging chunk (reused 4x)
    __shared__ ulonglong4 rowsP[MAXROWS];    // samp rows packed dup
    __shared__ float rowred[8][MAXROWS];     // per-warp row minima (unclamped)

    // ---- block -> (b, mq, j, nb, row range) ----
    const int B = blockIdx.x;
    int g, j, nb;
    if (B < 160) { g = B / 10; j = B - g * 10; nb = 10; }
    else { int Bp = B - 160; g = 16 + Bp / 9; j = Bp - (g - 16) * 9; nb = 9; }
    const int b  = g >> 2;
    const int mq = g & 3;
    const int rs  = (j * 2048) / nb;
    const int cnt = ((j + 1) * 2048) / nb - rs;

    const int tid = threadIdx.x;
    const int w   = tid >> 5;
    const int l   = tid & 31;

    const float* refb  = ref  + ((size_t)b * MM + mq * 2048) * 3;
    const float* sampb = samp + ((size_t)b * NN + rs) * 3;

    // ---- load samp rows (prescaled, packed-duplicated) ----
    if (tid < cnt) {
        float x = sampb[tid * 3 + 0];
        float y = sampb[tid * 3 + 1];
        float z = sampb[tid * 3 + 2];
        ulonglong4 r;
        r.x = pack2(-2.f * x);
        r.y = pack2(-2.f * y);
        r.z = pack2(-2.f * z);
        r.w = pack2(x * x + y * y + z * z);
        rowsP[tid] = r;
    }

    // ---- stage ref cols in 4 chunks of 512; pick up 8 cols as 4 packed pairs ----
    ull cxp[4], cyp[4], czp[4], cwp[4];
    for (int c = 0; c < 4; c++) {
        __syncthreads();
        for (int i = tid; i < 512; i += 256) {
            const float* p = refb + (c * 512 + i) * 3;
            float x = p[0], y = p[1], z = p[2];
            stage[i] = make_float4(x, y, z, x * x + y * y + z * z);
        }
        __syncthreads();
        if ((w >> 1) == c) {
            const int base = (w & 1) * 256 + l;
#pragma unroll
            for (int k = 0; k < 4; k++) {
                float4 a = stage[base + (2 * k) * 32];
                float4 d = stage[base + (2 * k + 1) * 32];
                cxp[k] = pack_ab(a.x, d.x);
                cyp[k] = pack_ab(a.y, d.y);
                czp[k] = pack_ab(a.z, d.z);
                cwp[k] = pack_ab(a.w, d.w);
            }
        }
    }
    __syncthreads();

    float colacc[8];
#pragma unroll
    for (int jj = 0; jj < 8; jj++) colacc[jj] = INFINITY;

    // ---- software-pipelined mainloop ----
    ull dprev[4];
    {   // prologue: FMA chains for row 0
        const ulonglong4 q = rowsP[0];
#pragma unroll
        for (int k = 0; k < 4; k++) {
            ull t = ffma2(q.z, czp[k], cwp[k]);
            t = ffma2(q.y, cyp[k], t);
            t = ffma2(q.x, cxp[k], t);
            dprev[k] = add2(t, q.w);
        }
    }

#pragma unroll 8
    for (int r = 1; r < cnt; r++) {
        // fma-pipe work for row r (independent of row r-1 mins below)
        const ulonglong4 q = rowsP[r];
        ull dcur[4];
#pragma unroll
        for (int k = 0; k < 4; k++) {
            ull t = ffma2(q.z, czp[k], cwp[k]);
            t = ffma2(q.y, cyp[k], t);
            t = ffma2(q.x, cxp[k], t);
            dcur[k] = add2(t, q.w);
        }
        // alu-pipe work for row r-1
        float pm[4];
#pragma unroll
        for (int k = 0; k < 4; k++) {
            float2 df = unpack2(dprev[k]);
            colacc[2 * k]     = fminf(colacc[2 * k], df.x);
            colacc[2 * k + 1] = fminf(colacc[2 * k + 1], df.y);
            pm[k] = fminf(df.x, df.y);
        }
        float rp = fminf(fminf(pm[0], pm[1]), fminf(pm[2], pm[3]));
        int rm = __reduce_min_sync(0xffffffffu, __float_as_int(rp));
        if (l == 0) rowred[w][r - 1] = __int_as_float(rm);
#pragma unroll
        for (int k = 0; k < 4; k++) dprev[k] = dcur[k];
    }

    {   // epilogue: mins for last row
        float pm[4];
#pragma unroll
        for (int k = 0; k < 4; k++) {
            float2 df = unpack2(dprev[k]);
            colacc[2 * k]     = fminf(colacc[2 * k], df.x);
            colacc[2 * k + 1] = fminf(colacc[2 * k + 1], df.y);
            pm[k] = fminf(df.x, df.y);
        }
        float rp = fminf(fminf(pm[0], pm[1]), fminf(pm[2], pm[3]));
        int rm = __reduce_min_sync(0xffffffffu, __float_as_int(rp));
        if (l == 0) rowred[w][cnt - 1] = __int_as_float(rm);
    }

    // ---- emit col partials (min over this block's rows) ----
    {
        const int mbase = mq * 2048 + w * 256 + l;
#pragma unroll
        for (int k = 0; k < 8; k++)
            g_col[j][b][mbase + k * 32] = colacc[k];   // unclamped
    }

    // ---- combine row partials across the 8 warps ----
    __syncthreads();
    for (int i = tid; i < cnt; i += 256) {
        float v = rowred[0][i];
#pragma unroll
        for (int k = 1; k < 8; k++) v = fminf(v, rowred[k][i]);
        g_row[mq][b][rs + i] = v;   // unclamped
    }
}

// Stage 1: combine partials, CLAMP, sqrt, partial sums.
// grid = (36, 16): pieces 0..3 = rows (512 samp points each),
// pieces 4..35 = cols (256 ref points each). One element per thread.
__global__ void __launch_bounds__(256) final1_kernel() {
    const int piece = blockIdx.x, b = blockIdx.y, tid = threadIdx.x;
    float sd = 0.f, ss = 0.f;
    if (piece < 4) {
        const int n0 = piece * 512;
        for (int n = n0 + tid; n < n0 + 512; n += 256) {
            float v = fminf(fminf(g_row[0][b][n], g_row[1][b][n]),
                            fminf(g_row[2][b][n], g_row[3][b][n]));
            v = fmaxf(v, 0.f);
            sd += v;
            ss += sqrtf(v);
        }
    } else {
        const int nb = (b < 4) ? 10 : 9;   // col slots for this batch
        const int m = (piece - 4) * 256 + tid;
        float v = g_col[0][b][m];
        for (int s = 1; s < nb; s++) v = fminf(v, g_col[s][b][m]);
        v = fmaxf(v, 0.f);
        sd = v;
        ss = sqrtf(v);
    }
    for (int o = 16; o > 0; o >>= 1) {
        sd += __shfl_down_sync(0xffffffffu, sd, o);
        ss += __shfl_down_sync(0xffffffffu, ss, o);
    }
    __shared__ float sh[2][8];
    if ((tid & 31) == 0) {
        sh[0][tid >> 5] = sd;
        sh[1][tid >> 5] = ss;
    }
    __syncthreads();
    if (tid < 8) {
        float a = sh[0][tid], c = sh[1][tid];
        for (int o = 4; o > 0; o >>= 1) {
            a += __shfl_down_sync(0xffu, a, o);
            c += __shfl_down_sync(0xffu, c, o);
        }
        if (tid == 0) {
            g_part[b][piece][0] = a;
            g_part[b][piece][1] = c;
        }
    }
}

__global__ void final2_kernel(float* __restrict__ out) {
    const int b = blockIdx.x;
    const int tid = threadIdx.x;   // 32 threads
    float rd = 0.f, rsq = 0.f, cd = 0.f, cs = 0.f;
    for (int p = tid; p < 36; p += 32) {
        float d = g_part[b][p][0];
        float s = g_part[b][p][1];
        if (p < 4) { rd += d; rsq += s; }
        else       { cd += d; cs  += s; }
    }
    for (int o = 16; o > 0; o >>= 1) {
        rd  += __shfl_down_sync(0xffffffffu, rd, o);
        rsq += __shfl_down_sync(0xffffffffu, rsq, o);
        cd  += __shfl_down_sync(0xffffffffu, cd, o);
        cs  += __shfl_down_sync(0xffffffffu, cs, o);
    }
    if (tid == 0) {
        float meanA  = rd  / (float)NN;
        float meanAs = rsq / (float)NN;
        float meanB  = cd  / (float)MM;
        float meanBs = cs  / (float)MM;
        out[b]      = 0.5f * (meanAs + meanBs);  // cd_p
        out[16 + b] = meanA + meanB;             // cd_t
    }
}

extern "C" void kernel_launch(void* const* d_in, const int* in_sizes, int n_in,
                              void* d_out, int out_size) {
    const float* ref;
    const float* samp;
    if (in_sizes[0] == BB * MM * 3) {
        ref = (const float*)d_in[0];
        samp = (const float*)d_in[1];
    } else {
        ref = (const float*)d_in[1];
        samp = (const float*)d_in[0];
    }
    float* out = (float*)d_out;

    chamfer_fused<<<592, 256>>>(samp, ref);
    final1_kernel<<<dim3(36, BB), 256>>>();
    final2_kernel<<<BB, 32>>>(out);
}

// round 17
// speedup vs baseline: 1.0248x; 1.0248x over previous
#include <cuda_runtime.h>
#include <math.h>

#define BB 16
#define NN 2048   // samp points (rows)
#define MM 8192   // ref points (cols)

// Scratch: partial minima (written, never read-modify — no init needed)
// Values UNCLAMPED (can be tiny-negative); final1 clamps.
__device__ float g_row[4][BB][NN];       // per m-quarter: min d2 for each samp point
__device__ float g_col[10][BB][MM];      // per in-group slot j: min d2 for each ref point

typedef unsigned long long ull;

__device__ __forceinline__ ull pack2(float v) {
    ull r;
    asm("mov.b64 %0, {%1, %1};" : "=l"(r) : "f"(v));
    return r;
}
__device__ __forceinline__ ull pack_ab(float a, float b) {
    ull r;
    asm("mov.b64 %0, {%1, %2};" : "=l"(r) : "f"(a), "f"(b));
    return r;
}
__device__ __forceinline__ ull ffma2(ull a, ull b, ull c) {
    ull d;
    asm("fma.rn.f32x2 %0, %1, %2, %3;" : "=l"(d) : "l"(a), "l"(b), "l"(c));
    return d;
}
__device__ __forceinline__ ull add2(ull a, ull b) {
    ull d;
    asm("add.rn.f32x2 %0, %1, %2;" : "=l"(d) : "l"(a), "l"(b));
    return d;
}
__device__ __forceinline__ float2 unpack2(ull v) {
    float2 f;
    asm("mov.b64 {%0, %1}, %2;" : "=f"(f.x), "=f"(f.y) : "l"(v));
    return f;
}

#define MAXROWS 228   // max rows per block (2048/9 rounded up)

// Single-wave kernel: EXACTLY 592 blocks = 148 SMs x 4 resident.
// 64 groups g=(b,mq) of 2048 rows x 2048 cols; batches 0-3: 10 blocks/group,
// batches 4-15: 9 blocks/group. Block j covers rows [j*2048/nb,(j+1)*2048/nb).
// Lane owns 8 cols as 4 f32x2 pairs; packed FMA chain; scalar FMNMX mins;
// one redux.sync.min.s32 per row (clamp deferred to final1).
// Block 0 additionally zeroes the 32 output floats (stream-ordered before final1).
__global__ void __launch_bounds__(256, 4) chamfer_fused(const float* __restrict__ samp,
                                                        const float* __restrict__ ref,
                                                        float* __restrict__ out) {
    __shared__ float4 stage[512];            // ref staging chunk (reused 4x)
    __shared__ ulonglong4 rowsP[MAXROWS];    // samp rows packed dup
    __shared__ float rowred[8][MAXROWS];     // per-warp row minima (unclamped)

    // ---- block -> (b, mq, j, nb, row range) ----
    const int B = blockIdx.x;
    int g, j, nb;
    if (B < 160) { g = B / 10; j = B - g * 10; nb = 10; }
    else { int Bp = B - 160; g = 16 + Bp / 9; j = Bp - (g - 16) * 9; nb = 9; }
    const int b  = g >> 2;
    const int mq = g & 3;
    const int rs  = (j * 2048) / nb;
    const int cnt = ((j + 1) * 2048) / nb - rs;

    const int tid = threadIdx.x;
    const int w   = tid >> 5;
    const int l   = tid & 31;

    if (B == 0 && tid < 32) out[tid] = 0.f;   // init outputs for final1's atomics

    const float* refb  = ref  + ((size_t)b * MM + mq * 2048) * 3;
    const float* sampb = samp + ((size_t)b * NN + rs) * 3;

    // ---- load samp rows (prescaled, packed-duplicated) ----
    if (tid < cnt) {
        float x = sampb[tid * 3 + 0];
        float y = sampb[tid * 3 + 1];
        float z = sampb[tid * 3 + 2];
        ulonglong4 r;
        r.x = pack2(-2.f * x);
        r.y = pack2(-2.f * y);
        r.z = pack2(-2.f * z);
        r.w = pack2(x * x + y * y + z * z);
        rowsP[tid] = r;
    }

    // ---- stage ref cols in 4 chunks of 512; pick up 8 cols as 4 packed pairs ----
    ull cxp[4], cyp[4], czp[4], cwp[4];
    for (int c = 0; c < 4; c++) {
        __syncthreads();
        for (int i = tid; i < 512; i += 256) {
            const float* p = refb + (c * 512 + i) * 3;
            float x = p[0], y = p[1], z = p[2];
            stage[i] = make_float4(x, y, z, x * x + y * y + z * z);
        }
        __syncthreads();
        if ((w >> 1) == c) {
            const int base = (w & 1) * 256 + l;
#pragma unroll
            for (int k = 0; k < 4; k++) {
                float4 a = stage[base + (2 * k) * 32];
                float4 d = stage[base + (2 * k + 1) * 32];
                cxp[k] = pack_ab(a.x, d.x);
                cyp[k] = pack_ab(a.y, d.y);
                czp[k] = pack_ab(a.z, d.z);
                cwp[k] = pack_ab(a.w, d.w);
            }
        }
    }
    __syncthreads();

    float colacc[8];
#pragma unroll
    for (int jj = 0; jj < 8; jj++) colacc[jj] = INFINITY;

    // ---- mainloop: packed FMA chain; 1 signed-int REDUX per row ----
#pragma unroll 8
    for (int r = 0; r < cnt; r++) {
        const ulonglong4 q = rowsP[r];
        float pm[4];
#pragma unroll
        for (int k = 0; k < 4; k++) {
            ull t = ffma2(q.z, czp[k], cwp[k]);
            t = ffma2(q.y, cyp[k], t);
            t = ffma2(q.x, cxp[k], t);
            ull d = add2(t, q.w);                 // full packed d2 pair
            float2 df = unpack2(d);
            colacc[2 * k]     = fminf(colacc[2 * k], df.x);
            colacc[2 * k + 1] = fminf(colacc[2 * k + 1], df.y);
            pm[k] = fminf(df.x, df.y);
        }
        float rp = fminf(fminf(pm[0], pm[1]), fminf(pm[2], pm[3]));
        int rm = __reduce_min_sync(0xffffffffu, __float_as_int(rp));
        if (l == 0) rowred[w][r] = __int_as_float(rm);
    }

    // ---- emit col partials (min over this block's rows) ----
    {
        const int mbase = mq * 2048 + w * 256 + l;
#pragma unroll
        for (int k = 0; k < 8; k++)
            g_col[j][b][mbase + k * 32] = colacc[k];   // unclamped
    }

    // ---- combine row partials across the 8 warps ----
    __syncthreads();
    for (int i = tid; i < cnt; i += 256) {
        float v = rowred[0][i];
#pragma unroll
        for (int k = 1; k < 8; k++) v = fminf(v, rowred[k][i]);
        g_row[mq][b][rs + i] = v;   // unclamped
    }
}

// Finalize: combine partials, CLAMP, sqrt, sum, and atomically accumulate the
// scaled contribution straight into out[] (out zeroed by chamfer block 0).
// grid = (36, 16): pieces 0..3 = rows (512 samp points each),
// pieces 4..35 = cols (256 ref points each). One element per thread.
// cd_p = 0.5*(rowSqSum/NN + colSqSum/MM); cd_t = rowSum/NN + colSum/MM.
__global__ void __launch_bounds__(256) final1_kernel(float* __restrict__ out) {
    const int piece = blockIdx.x, b = blockIdx.y, tid = threadIdx.x;
    float sd = 0.f, ss = 0.f;
    float inv;
    if (piece < 4) {
        inv = 1.f / (float)NN;
        const int n0 = piece * 512;
        for (int n = n0 + tid; n < n0 + 512; n += 256) {
            float v = fminf(fminf(g_row[0][b][n], g_row[1][b][n]),
                            fminf(g_row[2][b][n], g_row[3][b][n]));
            v = fmaxf(v, 0.f);
            sd += v;
            ss += sqrtf(v);
        }
    } else {
        inv = 1.f / (float)MM;
        const int nb = (b < 4) ? 10 : 9;   // col slots for this batch
        const int m = (piece - 4) * 256 + tid;
        float v = g_col[0][b][m];
        for (int s = 1; s < nb; s++) v = fminf(v, g_col[s][b][m]);
        v = fmaxf(v, 0.f);
        sd = v;
        ss = sqrtf(v);
    }
    for (int o = 16; o > 0; o >>= 1) {
        sd += __shfl_down_sync(0xffffffffu, sd, o);
        ss += __shfl_down_sync(0xffffffffu, ss, o);
    }
    __shared__ float sh[2][8];
    if ((tid & 31) == 0) {
        sh[0][tid >> 5] = sd;
        sh[1][tid >> 5] = ss;
    }
    __syncthreads();
    if (tid < 8) {
        float a = sh[0][tid], c = sh[1][tid];
        for (int o = 4; o > 0; o >>= 1) {
            a += __shfl_down_sync(0xffu, a, o);
            c += __shfl_down_sync(0xffu, c, o);
        }
        if (tid == 0) {
            atomicAdd(&out[b],      0.5f * c * inv);  // cd_p contribution
            atomicAdd(&out[16 + b], a * inv);         // cd_t contribution
        }
    }
}

extern "C" void kernel_launch(void* const* d_in, const int* in_sizes, int n_in,
                              void* d_out, int out_size) {
    const float* ref;
    const float* samp;
    if (in_sizes[0] == BB * MM * 3) {
        ref = (const float*)d_in[0];
        samp = (const float*)d_in[1];
    } else {
        ref = (const float*)d_in[1];
        samp = (const float*)d_in[0];
    }
    float* out = (float*)d_out;

    chamfer_fused<<<592, 256>>>(samp, ref, out);
    final1_kernel<<<dim3(36, BB), 256>>>(out);
}